// round 11
// baseline (speedup 1.0000x reference)
#include <cuda_runtime.h>
#include <math.h>

#define HEAD_SIZE   128
#define NUM_Q       32
#define NUM_K       8
#define NUM_QK      (NUM_Q + NUM_K)          // 40 heads get norm+rope
#define ROW_ELEMS   (48 * HEAD_SIZE)         // 6144 floats per token
#define V_OFFSET    (NUM_QK * HEAD_SIZE)     // 5120
#define EPS         1e-6f
#define GRID_CTAS   608                      // 152 SMs * 4 resident CTAs

__global__ __launch_bounds__(256, 4)
void rope_qknorm_kernel(const float* __restrict__ qkv,
                        const float* __restrict__ q_weight,
                        const float* __restrict__ k_weight,
                        const int*   __restrict__ positions,
                        float* __restrict__ out, int T)
{
    const int tid  = threadIdx.x;
    const int warp = tid >> 5;
    const int lane = tid & 31;

    // ---- loop invariants: weights + per-lane inv_freq ----
    const float2 wqa = __ldg((const float2*)q_weight + lane);
    const float2 wqb = __ldg((const float2*)q_weight + lane + 32);
    const float2 wka = __ldg((const float2*)k_weight + lane);
    const float2 wkb = __ldg((const float2*)k_weight + lane + 32);

    // Lane l needs rotary freqs j=2l, 2l+1. Mirror the reference's f32 math:
    //   inv_freq = 1.0f / powf(10000.0f, (2j)/128.0f)  -- position-independent,
    // hoisted out of the token loop.
    const float e0     = (float)(4 * lane)     / 128.0f;
    const float e1     = (float)(4 * lane + 2) / 128.0f;
    const float inv_f0 = 1.0f / powf(10000.0f, e0);
    const float inv_f1 = 1.0f / powf(10000.0f, e1);

    // ---- persistent grid-stride token loop (barrier-free body) ----
    for (int t = blockIdx.x; t < T; t += GRID_CTAS) {
        const float* __restrict__ row  = qkv + (size_t)t * ROW_ELEMS;
        float*       __restrict__ orow = out + (size_t)t * ROW_ELEMS;

        // PHASE 1: front-batch all 11 global loads (independent, MLP=11)
        float2 a[5], b[5];
        #pragma unroll
        for (int i = 0; i < 5; i++) {
            const int h = warp + i * 8;      // i=0..3 -> Q heads, i=4 -> K head
            const float2* __restrict__ hp = (const float2*)(row + h * HEAD_SIZE);
            a[i] = hp[lane];
            b[i] = hp[lane + 32];
        }
        const float4 v = ((const float4*)(row + V_OFFSET))[tid];

        // PHASE 2: per-lane sincos (overlapped with in-flight loads)
        //   arg = (float)pos * inv_freq ; sincosf == {sinf,cosf} bitwise.
        const float pos_f = (float)__ldg(positions + t);
        float2 c2, sn2;
        sincosf(pos_f * inv_f0, &sn2.x, &c2.x);
        sincosf(pos_f * inv_f1, &sn2.y, &c2.y);

        // PHASE 3: per-head RMS + rotate + store
        #pragma unroll
        for (int i = 0; i < 5; i++) {
            float ss = a[i].x * a[i].x + a[i].y * a[i].y
                     + b[i].x * b[i].x + b[i].y * b[i].y;
            #pragma unroll
            for (int o = 16; o; o >>= 1)
                ss += __shfl_xor_sync(0xffffffffu, ss, o);
            const float inv = rsqrtf(ss * (1.0f / HEAD_SIZE) + EPS);

            const int h = warp + i * 8;
            float2* __restrict__ op = (float2*)(orow + h * HEAD_SIZE);

            const float2 wa = (i < 4) ? wqa : wka;
            const float2 wb = (i < 4) ? wqb : wkb;

            // match reference order: (x * inv) * w
            const float ax = (a[i].x * inv) * wa.x;
            const float ay = (a[i].y * inv) * wa.y;
            const float bx = (b[i].x * inv) * wb.x;
            const float by = (b[i].y * inv) * wb.y;

            // NeoX rotate: pair (j, j+64), lane-local
            float2 o0, o1;
            o0.x = ax * c2.x - bx * sn2.x;
            o0.y = ay * c2.y - by * sn2.y;
            o1.x = bx * c2.x + ax * sn2.x;
            o1.y = by * c2.y + ay * sn2.y;

            op[lane]      = o0;
            op[lane + 32] = o1;
        }

        // V passthrough
        ((float4*)(orow + V_OFFSET))[tid] = v;
    }
}

extern "C" void kernel_launch(void* const* d_in, const int* in_sizes, int n_in,
                              void* d_out, int out_size)
{
    const float* qkv       = (const float*)d_in[0];
    const float* q_weight  = (const float*)d_in[1];
    const float* k_weight  = (const float*)d_in[2];
    const int*   positions = (const int*)  d_in[3];
    float*       out       = (float*)d_out;

    const int T = in_sizes[3];   // 8192 tokens
    const int grid = (T < GRID_CTAS) ? T : GRID_CTAS;
    rope_qknorm_kernel<<<grid, 256>>>(qkv, q_weight, k_weight, positions, out, T);
}

// round 12
// speedup vs baseline: 1.1038x; 1.1038x over previous
#include <cuda_runtime.h>
#include <math.h>

#define HEAD_SIZE   128
#define NUM_Q       32
#define NUM_K       8
#define NUM_QK      (NUM_Q + NUM_K)          // 40 heads get norm+rope
#define ROW_ELEMS   (48 * HEAD_SIZE)         // 6144 floats per token
#define V_OFFSET    (NUM_QK * HEAD_SIZE)     // 5120
#define EPS         1e-6f

__global__ __launch_bounds__(256, 4)
void rope_qknorm_kernel(const float* __restrict__ qkv,
                        const float* __restrict__ q_weight,
                        const float* __restrict__ k_weight,
                        const int*   __restrict__ positions,
                        float* __restrict__ out)
{
    __shared__ float s_cos[64];
    __shared__ float s_sin[64];

    const int t    = blockIdx.x;
    const int tid  = threadIdx.x;
    const int warp = tid >> 5;
    const int lane = tid & 31;

    const float* __restrict__ row  = qkv + (size_t)t * ROW_ELEMS;
    float*       __restrict__ orow = out + (size_t)t * ROW_ELEMS;

    // ================= PHASE 1: front-batch ALL global loads =================
    // Lane owns elems {2l,2l+1} (first half) and {2l+64,2l+65} (second half)
    // of each of its 5 heads. 10x LDG.64 + 1x LDG.128, all independent
    // (MLP=11 per thread). One CTA per token: independent CTAs per SM
    // interleave load/compute/store phases — measured better than any
    // persistent or pipelined variant.
    float2 a[5], b[5];
    #pragma unroll
    for (int i = 0; i < 5; i++) {
        const int h = warp + i * 8;      // i=0..3 -> Q heads, i=4 -> K head
        const float2* __restrict__ hp = (const float2*)(row + h * HEAD_SIZE);
        a[i] = hp[lane];
        b[i] = hp[lane + 32];
    }
    const float4 v = ((const float4*)(row + V_OFFSET))[tid];

    // weights (L1/L2-resident after first wave)
    const float2 wqa = __ldg((const float2*)q_weight + lane);
    const float2 wqb = __ldg((const float2*)q_weight + lane + 32);
    const float2 wka = __ldg((const float2*)k_weight + lane);
    const float2 wkb = __ldg((const float2*)k_weight + lane + 32);

    // ============ PHASE 2: sincos table, overlapped with loads ==============
    // Mirror the reference's f32 arithmetic EXACTLY:
    //   inv_freq = 1.0f / powf(10000.0f, (2j)/128.0f); arg = (float)pos * inv_freq
    if (tid < 64) {
        float e     = (float)(2 * tid) / 128.0f;
        float inv_f = 1.0f / powf(10000.0f, e);
        float pos_f = (float)positions[t];
        float arg   = pos_f * inv_f;
        s_cos[tid] = cosf(arg);
        s_sin[tid] = sinf(arg);
    }

    // ============ PHASE 3: per-head RMS (consumes loads, no cos/sin) ========
    float inv[5];
    #pragma unroll
    for (int i = 0; i < 5; i++) {
        float ss = a[i].x * a[i].x + a[i].y * a[i].y
                 + b[i].x * b[i].x + b[i].y * b[i].y;
        #pragma unroll
        for (int o = 16; o; o >>= 1)
            ss += __shfl_xor_sync(0xffffffffu, ss, o);
        inv[i] = rsqrtf(ss * (1.0f / HEAD_SIZE) + EPS);
    }

    __syncthreads();

    // ============ PHASE 4: rotate + store ===================================
    const float2 c2  = ((const float2*)s_cos)[lane];
    const float2 sn2 = ((const float2*)s_sin)[lane];

    #pragma unroll
    for (int i = 0; i < 5; i++) {
        const int h = warp + i * 8;
        float2* __restrict__ op = (float2*)(orow + h * HEAD_SIZE);

        const float2 wa = (i < 4) ? wqa : wka;
        const float2 wb = (i < 4) ? wqb : wkb;

        // match reference order: (x * inv) * w
        const float ax = (a[i].x * inv[i]) * wa.x;
        const float ay = (a[i].y * inv[i]) * wa.y;
        const float bx = (b[i].x * inv[i]) * wb.x;
        const float by = (b[i].y * inv[i]) * wb.y;

        // NeoX rotate: pair (j, j+64), lane-local
        float2 o0, o1;
        o0.x = ax * c2.x - bx * sn2.x;
        o0.y = ay * c2.y - by * sn2.y;
        o1.x = bx * c2.x + ax * sn2.x;
        o1.y = by * c2.y + ay * sn2.y;

        op[lane]      = o0;
        op[lane + 32] = o1;
    }

    // V passthrough
    ((float4*)(orow + V_OFFSET))[tid] = v;
}

extern "C" void kernel_launch(void* const* d_in, const int* in_sizes, int n_in,
                              void* d_out, int out_size)
{
    const float* qkv       = (const float*)d_in[0];
    const float* q_weight  = (const float*)d_in[1];
    const float* k_weight  = (const float*)d_in[2];
    const int*   positions = (const int*)  d_in[3];
    float*       out       = (float*)d_out;

    const int T = in_sizes[3];   // 8192 tokens
    rope_qknorm_kernel<<<T, 256>>>(qkv, q_weight, k_weight, positions, out);
}

// round 13
// speedup vs baseline: 1.1207x; 1.0153x over previous
#include <cuda_runtime.h>
#include <math.h>

#define HEAD_SIZE   128
#define NUM_Q       32
#define NUM_K       8
#define NUM_QK      (NUM_Q + NUM_K)          // 40 heads get norm+rope
#define ROW_ELEMS   (48 * HEAD_SIZE)         // 6144 floats per token
#define V_OFFSET    (NUM_QK * HEAD_SIZE)     // 5120
#define EPS         1e-6f

__global__ __launch_bounds__(256, 4)
void rope_qknorm_kernel(const float* __restrict__ qkv,
                        const float* __restrict__ q_weight,
                        const float* __restrict__ k_weight,
                        const int*   __restrict__ positions,
                        float* __restrict__ out)
{
    __shared__ float s_cos[64];
    __shared__ float s_sin[64];

    const int t    = blockIdx.x;
    const int tid  = threadIdx.x;
    const int warp = tid >> 5;
    const int lane = tid & 31;

    const float* __restrict__ row  = qkv + (size_t)t * ROW_ELEMS;
    float*       __restrict__ orow = out + (size_t)t * ROW_ELEMS;

    // ================= PHASE 1: front-batch ALL global loads =================
    // Lane owns elems {2l,2l+1} (first half) and {2l+64,2l+65} (second half)
    // of each of its 5 heads. 10x LDG.64 + 1x LDG.128, all independent
    // (MLP=11 per thread). One CTA per token: independent CTAs per SM
    // interleave load/compute/store phases — measured better than any
    // persistent or pipelined variant.
    float2 a[5], b[5];
    #pragma unroll
    for (int i = 0; i < 5; i++) {
        const int h = warp + i * 8;      // i=0..3 -> Q heads, i=4 -> K head
        const float2* __restrict__ hp = (const float2*)(row + h * HEAD_SIZE);
        a[i] = hp[lane];
        b[i] = hp[lane + 32];
    }
    const float4 v = ((const float4*)(row + V_OFFSET))[tid];

    // weights (L1/L2-resident after first wave)
    const float2 wqa = __ldg((const float2*)q_weight + lane);
    const float2 wqb = __ldg((const float2*)q_weight + lane + 32);
    const float2 wka = __ldg((const float2*)k_weight + lane);
    const float2 wkb = __ldg((const float2*)k_weight + lane + 32);

    // ============ PHASE 2: sincos table, overlapped with loads ==============
    // Mirror the reference's f32 arithmetic EXACTLY:
    //   inv_freq = 1.0f / powf(10000.0f, (2j)/128.0f); arg = (float)pos * inv_freq
    if (tid < 64) {
        float e     = (float)(2 * tid) / 128.0f;
        float inv_f = 1.0f / powf(10000.0f, e);
        float pos_f = (float)positions[t];
        float arg   = pos_f * inv_f;
        s_cos[tid] = cosf(arg);
        s_sin[tid] = sinf(arg);
    }

    // ============ PHASE 3: per-head RMS (consumes loads, no cos/sin) ========
    float inv[5];
    #pragma unroll
    for (int i = 0; i < 5; i++) {
        float ss = a[i].x * a[i].x + a[i].y * a[i].y
                 + b[i].x * b[i].x + b[i].y * b[i].y;
        #pragma unroll
        for (int o = 16; o; o >>= 1)
            ss += __shfl_xor_sync(0xffffffffu, ss, o);
        inv[i] = rsqrtf(ss * (1.0f / HEAD_SIZE) + EPS);
    }

    __syncthreads();

    // ============ PHASE 4: rotate + store ===================================
    const float2 c2  = ((const float2*)s_cos)[lane];
    const float2 sn2 = ((const float2*)s_sin)[lane];

    #pragma unroll
    for (int i = 0; i < 5; i++) {
        const int h = warp + i * 8;
        float2* __restrict__ op = (float2*)(orow + h * HEAD_SIZE);

        const float2 wa = (i < 4) ? wqa : wka;
        const float2 wb = (i < 4) ? wqb : wkb;

        // match reference order: (x * inv) * w
        const float ax = (a[i].x * inv[i]) * wa.x;
        const float ay = (a[i].y * inv[i]) * wa.y;
        const float bx = (b[i].x * inv[i]) * wb.x;
        const float by = (b[i].y * inv[i]) * wb.y;

        // NeoX rotate: pair (j, j+64), lane-local
        float2 o0, o1;
        o0.x = ax * c2.x - bx * sn2.x;
        o0.y = ay * c2.y - by * sn2.y;
        o1.x = bx * c2.x + ax * sn2.x;
        o1.y = by * c2.y + ay * sn2.y;

        op[lane]      = o0;
        op[lane + 32] = o1;
    }

    // V passthrough
    ((float4*)(orow + V_OFFSET))[tid] = v;
}

extern "C" void kernel_launch(void* const* d_in, const int* in_sizes, int n_in,
                              void* d_out, int out_size)
{
    const float* qkv       = (const float*)d_in[0];
    const float* q_weight  = (const float*)d_in[1];
    const float* k_weight  = (const float*)d_in[2];
    const int*   positions = (const int*)  d_in[3];
    float*       out       = (float*)d_out;

    const int T = in_sizes[3];   // 8192 tokens
    rope_qknorm_kernel<<<T, 256>>>(qkv, q_weight, k_weight, positions, out);
}

// round 14
// speedup vs baseline: 1.1311x; 1.0093x over previous
#include <cuda_runtime.h>
#include <math.h>

#define HEAD_SIZE   128
#define NUM_Q       32
#define NUM_K       8
#define NUM_QK      (NUM_Q + NUM_K)          // 40 heads get norm+rope
#define ROW_ELEMS   (48 * HEAD_SIZE)         // 6144 floats per token
#define V_OFFSET    (NUM_QK * HEAD_SIZE)     // 5120
#define EPS         1e-6f

__global__ __launch_bounds__(256, 4)
void rope_qknorm_kernel(const float* __restrict__ qkv,
                        const float* __restrict__ q_weight,
                        const float* __restrict__ k_weight,
                        const int*   __restrict__ positions,
                        float* __restrict__ out)
{
    __shared__ float s_cos[64];
    __shared__ float s_sin[64];

    const int t    = blockIdx.x;
    const int tid  = threadIdx.x;
    const int warp = tid >> 5;
    const int lane = tid & 31;

    const float* __restrict__ row  = qkv + (size_t)t * ROW_ELEMS;
    float*       __restrict__ orow = out + (size_t)t * ROW_ELEMS;

    // ================= PHASE 1: front-batch ALL global loads =================
    // Lane owns elems {2l,2l+1} (first half) and {2l+64,2l+65} (second half)
    // of each of its 5 heads. 10x LDG.64 + 1x LDG.128, all independent
    // (MLP=11 per thread). One CTA per token: independent CTAs per SM
    // interleave load/compute/store phases — measured better than any
    // persistent or pipelined variant.
    float2 a[5], b[5];
    #pragma unroll
    for (int i = 0; i < 5; i++) {
        const int h = warp + i * 8;      // i=0..3 -> Q heads, i=4 -> K head
        const float2* __restrict__ hp = (const float2*)(row + h * HEAD_SIZE);
        a[i] = hp[lane];
        b[i] = hp[lane + 32];
    }
    const float4 v = ((const float4*)(row + V_OFFSET))[tid];

    // weights (L1/L2-resident after first wave)
    const float2 wqa = __ldg((const float2*)q_weight + lane);
    const float2 wqb = __ldg((const float2*)q_weight + lane + 32);
    const float2 wka = __ldg((const float2*)k_weight + lane);
    const float2 wkb = __ldg((const float2*)k_weight + lane + 32);

    // ============ PHASE 2: sincos table, overlapped with loads ==============
    // Mirror the reference's f32 arithmetic EXACTLY:
    //   inv_freq = 1.0f / powf(10000.0f, (2j)/128.0f); arg = (float)pos * inv_freq
    if (tid < 64) {
        float e     = (float)(2 * tid) / 128.0f;
        float inv_f = 1.0f / powf(10000.0f, e);
        float pos_f = (float)positions[t];
        float arg   = pos_f * inv_f;
        s_cos[tid] = cosf(arg);
        s_sin[tid] = sinf(arg);
    }

    // ============ PHASE 3: per-head RMS (consumes loads, no cos/sin) ========
    float inv[5];
    #pragma unroll
    for (int i = 0; i < 5; i++) {
        float ss = a[i].x * a[i].x + a[i].y * a[i].y
                 + b[i].x * b[i].x + b[i].y * b[i].y;
        #pragma unroll
        for (int o = 16; o; o >>= 1)
            ss += __shfl_xor_sync(0xffffffffu, ss, o);
        inv[i] = rsqrtf(ss * (1.0f / HEAD_SIZE) + EPS);
    }

    __syncthreads();

    // ============ PHASE 4: rotate + store ===================================
    const float2 c2  = ((const float2*)s_cos)[lane];
    const float2 sn2 = ((const float2*)s_sin)[lane];

    #pragma unroll
    for (int i = 0; i < 5; i++) {
        const int h = warp + i * 8;
        float2* __restrict__ op = (float2*)(orow + h * HEAD_SIZE);

        const float2 wa = (i < 4) ? wqa : wka;
        const float2 wb = (i < 4) ? wqb : wkb;

        // match reference order: (x * inv) * w
        const float ax = (a[i].x * inv[i]) * wa.x;
        const float ay = (a[i].y * inv[i]) * wa.y;
        const float bx = (b[i].x * inv[i]) * wb.x;
        const float by = (b[i].y * inv[i]) * wb.y;

        // NeoX rotate: pair (j, j+64), lane-local
        float2 o0, o1;
        o0.x = ax * c2.x - bx * sn2.x;
        o0.y = ay * c2.y - by * sn2.y;
        o1.x = bx * c2.x + ax * sn2.x;
        o1.y = by * c2.y + ay * sn2.y;

        op[lane]      = o0;
        op[lane + 32] = o1;
    }

    // V passthrough
    ((float4*)(orow + V_OFFSET))[tid] = v;
}

extern "C" void kernel_launch(void* const* d_in, const int* in_sizes, int n_in,
                              void* d_out, int out_size)
{
    const float* qkv       = (const float*)d_in[0];
    const float* q_weight  = (const float*)d_in[1];
    const float* k_weight  = (const float*)d_in[2];
    const int*   positions = (const int*)  d_in[3];
    float*       out       = (float*)d_out;

    const int T = in_sizes[3];   // 8192 tokens
    rope_qknorm_kernel<<<T, 256>>>(qkv, q_weight, k_weight, positions, out);
}